// round 3
// baseline (speedup 1.0000x reference)
#include <cuda_runtime.h>
#include <stdint.h>

// Problem shape (fixed by the dataset): B=4, S=4096, H=4096
#define H_DIM   4096
#define N_ROWS  16384            // B*S
#define N_ELEMS (N_ROWS * (size_t)H_DIM)   // 64M
#define EPS_F   1e-6f

// Scratch (no allocation allowed in kernel_launch)
__device__ float        g_inv_rms[N_ROWS];
__device__ unsigned int g_max_bits;
__device__ float        g_inv_scale;

// ---------------------------------------------------------------------------
// Kernel 0: reset global max (makes graph replays deterministic)
// ---------------------------------------------------------------------------
__global__ void k_init() {
    g_max_bits = 0u;
}

// ---------------------------------------------------------------------------
// Kernel 1: one CTA per row.
//   x = x1 + x2   -> write to out_x
//   inv_rms = rsqrt(mean(x^2) + eps) -> g_inv_rms[row]
//   block_max = max|x * gamma| * inv_rms -> atomicMax(g_max_bits)
// 512 threads, each handles 2 float4 (8 elems).
// ---------------------------------------------------------------------------
__global__ __launch_bounds__(512, 2)
void k_pass1(const float* __restrict__ x1,
             const float* __restrict__ x2,
             const float* __restrict__ gamma,
             float* __restrict__ out_x)
{
    const int row = blockIdx.x;
    const int t   = threadIdx.x;           // 0..511
    const size_t base = (size_t)row * H_DIM;

    const float4* a4 = (const float4*)(x1 + base);
    const float4* b4 = (const float4*)(x2 + base);
    float4*       o4 = (float4*)(out_x + base);
    const float4* g4 = (const float4*)gamma;

    // two float4 chunks per thread: vec-index t and t+512 (row has 1024 vec4)
    float4 a0 = a4[t];
    float4 a1 = a4[t + 512];
    float4 b0 = b4[t];
    float4 b1 = b4[t + 512];

    float4 v0, v1;
    v0.x = a0.x + b0.x; v0.y = a0.y + b0.y; v0.z = a0.z + b0.z; v0.w = a0.w + b0.w;
    v1.x = a1.x + b1.x; v1.y = a1.y + b1.y; v1.z = a1.z + b1.z; v1.w = a1.w + b1.w;

    o4[t]       = v0;
    o4[t + 512] = v1;

    // sum of squares
    float ss = v0.x*v0.x + v0.y*v0.y + v0.z*v0.z + v0.w*v0.w
             + v1.x*v1.x + v1.y*v1.y + v1.z*v1.z + v1.w*v1.w;

    // block reduce sum (16 warps)
    __shared__ float s_red[16];
    __shared__ float s_inv;
    const int lane = t & 31;
    const int wid  = t >> 5;

    #pragma unroll
    for (int off = 16; off > 0; off >>= 1)
        ss += __shfl_xor_sync(0xffffffffu, ss, off);
    if (lane == 0) s_red[wid] = ss;
    __syncthreads();
    if (wid == 0) {
        float s = (lane < 16) ? s_red[lane] : 0.0f;
        #pragma unroll
        for (int off = 8; off > 0; off >>= 1)
            s += __shfl_xor_sync(0xffffffffu, s, off);
        if (lane == 0) {
            float inv = rsqrtf(s * (1.0f / H_DIM) + EPS_F);
            g_inv_rms[row] = inv;
            s_inv = inv;
        }
    }
    __syncthreads();
    const float inv = s_inv;

    // local max of |x * gamma|
    float4 gm0 = g4[t];
    float4 gm1 = g4[t + 512];
    float m = fabsf(v0.x * gm0.x);
    m = fmaxf(m, fabsf(v0.y * gm0.y));
    m = fmaxf(m, fabsf(v0.z * gm0.z));
    m = fmaxf(m, fabsf(v0.w * gm0.w));
    m = fmaxf(m, fabsf(v1.x * gm1.x));
    m = fmaxf(m, fabsf(v1.y * gm1.y));
    m = fmaxf(m, fabsf(v1.z * gm1.z));
    m = fmaxf(m, fabsf(v1.w * gm1.w));

    // block reduce max (reuse shared after sync)
    #pragma unroll
    for (int off = 16; off > 0; off >>= 1)
        m = fmaxf(m, __shfl_xor_sync(0xffffffffu, m, off));
    __syncthreads();   // protect s_red reuse
    if (lane == 0) s_red[wid] = m;
    __syncthreads();
    if (wid == 0) {
        float mm = (lane < 16) ? s_red[lane] : 0.0f;
        #pragma unroll
        for (int off = 8; off > 0; off >>= 1)
            mm = fmaxf(mm, __shfl_xor_sync(0xffffffffu, mm, off));
        if (lane == 0) {
            // all candidates >= 0 so uint ordering == float ordering
            atomicMax(&g_max_bits, __float_as_uint(mm * inv));
        }
    }
}

// ---------------------------------------------------------------------------
// Kernel 2: scalar epilogue — compute scale, write scale1/scale2, stash 127/max
// ---------------------------------------------------------------------------
__global__ void k_mid(float* __restrict__ out_scales)
{
    const float mx = __uint_as_float(g_max_bits);
    const float scale = mx * (1.0f / 127.0f);
    g_inv_scale = 127.0f / mx;
    out_scales[0] = scale;   // scale1
    out_scales[1] = scale;   // scale2
}

// ---------------------------------------------------------------------------
// Kernel 3: quantize. Grid-stride-free: exactly one thread per float4.
//   q = clamp(rint(x * inv_rms[row] * gamma[col] * (127/max)), -128, 127)
//   write q (as float32) to both y1 and y2 regions.
// ---------------------------------------------------------------------------
__global__ __launch_bounds__(256, 4)
void k_pass2(const float* __restrict__ xin,
             const float* __restrict__ gamma,
             float* __restrict__ y1,
             float* __restrict__ y2)
{
    const size_t v = (size_t)blockIdx.x * blockDim.x + threadIdx.x;  // float4 idx
    const size_t e = v << 2;                 // element idx
    const int row = (int)(e >> 12);          // /4096
    const int col = (int)(e & 4095);

    const float4 xv = ((const float4*)xin)[v];
    const float4 gv = *(const float4*)(gamma + col);
    const float inv = g_inv_rms[row];
    const float is  = g_inv_scale;
    const float s   = inv * is;              // combine: x * gamma * inv_rms * inv_scale

    float4 q;
    q.x = fminf(fmaxf(rintf(xv.x * gv.x * s), -128.0f), 127.0f);
    q.y = fminf(fmaxf(rintf(xv.y * gv.y * s), -128.0f), 127.0f);
    q.z = fminf(fmaxf(rintf(xv.z * gv.z * s), -128.0f), 127.0f);
    q.w = fminf(fmaxf(rintf(xv.w * gv.w * s), -128.0f), 127.0f);

    ((float4*)y1)[v] = q;
    ((float4*)y2)[v] = q;
}

// ---------------------------------------------------------------------------
// Launch: out layout (float32): [y1 (64M)] [y2 (64M)] [x (64M)] [scale1] [scale2]
// ---------------------------------------------------------------------------
extern "C" void kernel_launch(void* const* d_in, const int* in_sizes, int n_in,
                              void* d_out, int out_size)
{
    const float* x1    = (const float*)d_in[0];
    const float* x2    = (const float*)d_in[1];
    const float* gamma = (const float*)d_in[2];
    // d_in[3], d_in[4] = smooth_scale1/2 — unused by the reference

    float* out    = (float*)d_out;
    float* y1     = out;
    float* y2     = out + N_ELEMS;
    float* out_x  = out + 2 * N_ELEMS;
    float* scales = out + 3 * N_ELEMS;

    k_init<<<1, 1>>>();
    k_pass1<<<N_ROWS, 512>>>(x1, x2, gamma, out_x);
    k_mid<<<1, 1>>>(scales);
    const int vec4 = (int)(N_ELEMS / 4);          // 16M
    k_pass2<<<vec4 / 256, 256>>>(out_x, gamma, y1, y2);
}

// round 4
// speedup vs baseline: 1.0081x; 1.0081x over previous
#include <cuda_runtime.h>
#include <stdint.h>

// Problem shape (fixed by the dataset): B=4, S=4096, H=4096
#define H_DIM   4096
#define N_ROWS  16384                       // B*S
#define N_ELEMS (N_ROWS * (size_t)H_DIM)    // 64M
#define EPS_F   1e-6f

// Scratch (no allocation allowed in kernel_launch)
__device__ float        g_inv_rms[N_ROWS];
__device__ unsigned int g_max_bits;         // zero-initialized at module load
__device__ float        g_inv_scale;

// ---------------------------------------------------------------------------
// Kernel 1: one CTA per row.
//   x = x1 + x2   -> write to out_x (streaming store)
//   inv_rms = rsqrt(mean(x^2) + eps) -> g_inv_rms[row]
//   block_max = max|x * gamma| * inv_rms -> atomicMax(g_max_bits)
// 512 threads, each handles 2 float4 (8 elems). All bulk streams use
// evict-first policy (no L2 reuse possible: 256MB working set > 126MB L2).
// ---------------------------------------------------------------------------
__global__ __launch_bounds__(512, 2)
void k_pass1(const float* __restrict__ x1,
             const float* __restrict__ x2,
             const float* __restrict__ gamma,
             float* __restrict__ out_x)
{
    const int row = blockIdx.x;
    const int t   = threadIdx.x;           // 0..511
    const size_t base = (size_t)row * H_DIM;

    const float4* a4 = (const float4*)(x1 + base);
    const float4* b4 = (const float4*)(x2 + base);
    float4*       o4 = (float4*)(out_x + base);
    const float4* g4 = (const float4*)gamma;

    // two float4 chunks per thread: vec-index t and t+512 (row has 1024 vec4)
    float4 a0 = __ldcs(a4 + t);
    float4 a1 = __ldcs(a4 + t + 512);
    float4 b0 = __ldcs(b4 + t);
    float4 b1 = __ldcs(b4 + t + 512);

    float4 v0, v1;
    v0.x = a0.x + b0.x; v0.y = a0.y + b0.y; v0.z = a0.z + b0.z; v0.w = a0.w + b0.w;
    v1.x = a1.x + b1.x; v1.y = a1.y + b1.y; v1.z = a1.z + b1.z; v1.w = a1.w + b1.w;

    __stcs(o4 + t,       v0);
    __stcs(o4 + t + 512, v1);

    // sum of squares
    float ss = v0.x*v0.x + v0.y*v0.y + v0.z*v0.z + v0.w*v0.w
             + v1.x*v1.x + v1.y*v1.y + v1.z*v1.z + v1.w*v1.w;

    // block reduce sum (16 warps)
    __shared__ float s_red[16];
    __shared__ float s_inv;
    const int lane = t & 31;
    const int wid  = t >> 5;

    #pragma unroll
    for (int off = 16; off > 0; off >>= 1)
        ss += __shfl_xor_sync(0xffffffffu, ss, off);
    if (lane == 0) s_red[wid] = ss;
    __syncthreads();
    if (wid == 0) {
        float s = (lane < 16) ? s_red[lane] : 0.0f;
        #pragma unroll
        for (int off = 8; off > 0; off >>= 1)
            s += __shfl_xor_sync(0xffffffffu, s, off);
        if (lane == 0) {
            float inv = rsqrtf(s * (1.0f / H_DIM) + EPS_F);
            g_inv_rms[row] = inv;
            s_inv = inv;
        }
    }
    __syncthreads();
    const float inv = s_inv;

    // local max of |x * gamma|  (gamma: 16KB, stays L2/L1 resident -> default ld)
    float4 gm0 = g4[t];
    float4 gm1 = g4[t + 512];
    float m = fabsf(v0.x * gm0.x);
    m = fmaxf(m, fabsf(v0.y * gm0.y));
    m = fmaxf(m, fabsf(v0.z * gm0.z));
    m = fmaxf(m, fabsf(v0.w * gm0.w));
    m = fmaxf(m, fabsf(v1.x * gm1.x));
    m = fmaxf(m, fabsf(v1.y * gm1.y));
    m = fmaxf(m, fabsf(v1.z * gm1.z));
    m = fmaxf(m, fabsf(v1.w * gm1.w));

    // block reduce max (reuse shared after sync)
    #pragma unroll
    for (int off = 16; off > 0; off >>= 1)
        m = fmaxf(m, __shfl_xor_sync(0xffffffffu, m, off));
    __syncthreads();   // protect s_red reuse
    if (lane == 0) s_red[wid] = m;
    __syncthreads();
    if (wid == 0) {
        float mm = (lane < 16) ? s_red[lane] : 0.0f;
        #pragma unroll
        for (int off = 8; off > 0; off >>= 1)
            mm = fmaxf(mm, __shfl_xor_sync(0xffffffffu, mm, off));
        if (lane == 0) {
            // all candidates >= 0 so uint ordering == float ordering
            atomicMax(&g_max_bits, __float_as_uint(mm * inv));
        }
    }
}

// ---------------------------------------------------------------------------
// Kernel 2: scalar epilogue — write scale1/scale2, stash 127/max, and reset
// the accumulator so the next graph replay starts clean (deterministic).
// ---------------------------------------------------------------------------
__global__ void k_mid(float* __restrict__ out_scales)
{
    const float mx = __uint_as_float(g_max_bits);
    const float scale = mx * (1.0f / 127.0f);
    g_inv_scale = 127.0f / mx;
    out_scales[0] = scale;   // scale1
    out_scales[1] = scale;   // scale2
    g_max_bits = 0u;         // reset for next replay (runs after all pass1 atomics)
}

// ---------------------------------------------------------------------------
// Kernel 3: quantize. Each block covers half a row (512 consecutive float4),
// so inv_rms is uniform per block. 2 float4 per thread, block-strided for
// fully-coalesced 128B transactions and front-batched loads (MLP).
//   q = clamp(rint(x * inv_rms[row] * gamma[col] * (127/max)), -128, 127)
//   written (as float32) to both y1 and y2 regions with streaming stores.
// ---------------------------------------------------------------------------
__global__ __launch_bounds__(256, 8)
void k_pass2(const float* __restrict__ xin,
             const float* __restrict__ gamma,
             float* __restrict__ y1,
             float* __restrict__ y2)
{
    const int t = threadIdx.x;
    const size_t v0 = (size_t)blockIdx.x * 512 + t;   // float4 index
    const size_t v1 = v0 + 256;
    const int row = (int)(v0 >> 10);                  // 1024 vec4 per row

    const float4* x4 = (const float4*)xin;
    const float4* g4 = (const float4*)gamma;

    float4 xa = __ldcs(x4 + v0);
    float4 xb = __ldcs(x4 + v1);
    float4 ga = g4[v0 & 1023];
    float4 gb = g4[v1 & 1023];

    const float s = g_inv_rms[row] * g_inv_scale;     // fold both scalars

    float4 qa, qb;
    qa.x = fminf(fmaxf(rintf(xa.x * ga.x * s), -128.0f), 127.0f);
    qa.y = fminf(fmaxf(rintf(xa.y * ga.y * s), -128.0f), 127.0f);
    qa.z = fminf(fmaxf(rintf(xa.z * ga.z * s), -128.0f), 127.0f);
    qa.w = fminf(fmaxf(rintf(xa.w * ga.w * s), -128.0f), 127.0f);
    qb.x = fminf(fmaxf(rintf(xb.x * gb.x * s), -128.0f), 127.0f);
    qb.y = fminf(fmaxf(rintf(xb.y * gb.y * s), -128.0f), 127.0f);
    qb.z = fminf(fmaxf(rintf(xb.z * gb.z * s), -128.0f), 127.0f);
    qb.w = fminf(fmaxf(rintf(xb.w * gb.w * s), -128.0f), 127.0f);

    __stcs((float4*)y1 + v0, qa);
    __stcs((float4*)y1 + v1, qb);
    __stcs((float4*)y2 + v0, qa);
    __stcs((float4*)y2 + v1, qb);
}

// ---------------------------------------------------------------------------
// Launch: out layout (float32): [y1 (64M)] [y2 (64M)] [x (64M)] [scale1] [scale2]
// ---------------------------------------------------------------------------
extern "C" void kernel_launch(void* const* d_in, const int* in_sizes, int n_in,
                              void* d_out, int out_size)
{
    const float* x1    = (const float*)d_in[0];
    const float* x2    = (const float*)d_in[1];
    const float* gamma = (const float*)d_in[2];
    // d_in[3], d_in[4] = smooth_scale1/2 — unused by the reference

    float* out    = (float*)d_out;
    float* y1     = out;
    float* y2     = out + N_ELEMS;
    float* out_x  = out + 2 * N_ELEMS;
    float* scales = out + 3 * N_ELEMS;

    k_pass1<<<N_ROWS, 512>>>(x1, x2, gamma, out_x);
    k_mid<<<1, 1>>>(scales);
    const int vec4   = (int)(N_ELEMS / 4);            // 16M float4
    const int blocks = vec4 / 512;                    // 32768
    k_pass2<<<blocks, 256>>>(out_x, gamma, y1, y2);
}

// round 5
// speedup vs baseline: 1.0271x; 1.0189x over previous
#include <cuda_runtime.h>
#include <stdint.h>

// Problem shape (fixed by the dataset): B=4, S=4096, H=4096
#define H_DIM   4096
#define N_ROWS  16384                       // B*S
#define N_ELEMS (N_ROWS * (size_t)H_DIM)    // 64M
#define EPS_F   1e-6f

// Scratch (no allocation allowed in kernel_launch)
__device__ float        g_inv_rms[N_ROWS];
__device__ unsigned int g_max_bits;         // zero-initialized at module load
__device__ float        g_inv_scale;

// ---------------------------------------------------------------------------
// Kernel 1: one CTA per row.
//   x = x1 + x2   -> write to out_x (evict-NORMAL store: we want the tail of
//                    x to stay L2-resident for pass2's reversed consumption)
//   inv_rms = rsqrt(mean(x^2) + eps) -> g_inv_rms[row]
//   block_max = max|x * gamma| * inv_rms -> atomicMax(g_max_bits)
// x1/x2 reads are evict-first (zero reuse) so they don't displace x lines.
// ---------------------------------------------------------------------------
__global__ __launch_bounds__(512, 2)
void k_pass1(const float* __restrict__ x1,
             const float* __restrict__ x2,
             const float* __restrict__ gamma,
             float* __restrict__ out_x)
{
    const int row = blockIdx.x;
    const int t   = threadIdx.x;           // 0..511
    const size_t base = (size_t)row * H_DIM;

    const float4* a4 = (const float4*)(x1 + base);
    const float4* b4 = (const float4*)(x2 + base);
    float4*       o4 = (float4*)(out_x + base);
    const float4* g4 = (const float4*)gamma;

    // two float4 chunks per thread: vec-index t and t+512 (row has 1024 vec4)
    float4 a0 = __ldcs(a4 + t);
    float4 a1 = __ldcs(a4 + t + 512);
    float4 b0 = __ldcs(b4 + t);
    float4 b1 = __ldcs(b4 + t + 512);

    float4 v0, v1;
    v0.x = a0.x + b0.x; v0.y = a0.y + b0.y; v0.z = a0.z + b0.z; v0.w = a0.w + b0.w;
    v1.x = a1.x + b1.x; v1.y = a1.y + b1.y; v1.z = a1.z + b1.z; v1.w = a1.w + b1.w;

    // evict-normal stores: retain as much of x in L2 as possible for pass2
    o4[t]       = v0;
    o4[t + 512] = v1;

    // sum of squares
    float ss = v0.x*v0.x + v0.y*v0.y + v0.z*v0.z + v0.w*v0.w
             + v1.x*v1.x + v1.y*v1.y + v1.z*v1.z + v1.w*v1.w;

    // block reduce sum (16 warps)
    __shared__ float s_red[16];
    __shared__ float s_inv;
    const int lane = t & 31;
    const int wid  = t >> 5;

    #pragma unroll
    for (int off = 16; off > 0; off >>= 1)
        ss += __shfl_xor_sync(0xffffffffu, ss, off);
    if (lane == 0) s_red[wid] = ss;
    __syncthreads();
    if (wid == 0) {
        float s = (lane < 16) ? s_red[lane] : 0.0f;
        #pragma unroll
        for (int off = 8; off > 0; off >>= 1)
            s += __shfl_xor_sync(0xffffffffu, s, off);
        if (lane == 0) {
            float inv = rsqrtf(s * (1.0f / H_DIM) + EPS_F);
            g_inv_rms[row] = inv;
            s_inv = inv;
        }
    }
    __syncthreads();
    const float inv = s_inv;

    // local max of |x * gamma|  (gamma: 16KB, L1/L2 resident -> default ld)
    float4 gm0 = g4[t];
    float4 gm1 = g4[t + 512];
    float m = fabsf(v0.x * gm0.x);
    m = fmaxf(m, fabsf(v0.y * gm0.y));
    m = fmaxf(m, fabsf(v0.z * gm0.z));
    m = fmaxf(m, fabsf(v0.w * gm0.w));
    m = fmaxf(m, fabsf(v1.x * gm1.x));
    m = fmaxf(m, fabsf(v1.y * gm1.y));
    m = fmaxf(m, fabsf(v1.z * gm1.z));
    m = fmaxf(m, fabsf(v1.w * gm1.w));

    // block reduce max (reuse shared after sync)
    #pragma unroll
    for (int off = 16; off > 0; off >>= 1)
        m = fmaxf(m, __shfl_xor_sync(0xffffffffu, m, off));
    __syncthreads();   // protect s_red reuse
    if (lane == 0) s_red[wid] = m;
    __syncthreads();
    if (wid == 0) {
        float mm = (lane < 16) ? s_red[lane] : 0.0f;
        #pragma unroll
        for (int off = 8; off > 0; off >>= 1)
            mm = fmaxf(mm, __shfl_xor_sync(0xffffffffu, mm, off));
        if (lane == 0) {
            // all candidates >= 0 so uint ordering == float ordering
            atomicMax(&g_max_bits, __float_as_uint(mm * inv));
        }
    }
}

// ---------------------------------------------------------------------------
// Kernel 2: scalar epilogue — write scale1/scale2, stash 127/max, and reset
// the accumulator so the next graph replay starts clean (deterministic).
// Tiny: does not disturb L2-resident x lines.
// ---------------------------------------------------------------------------
__global__ void k_mid(float* __restrict__ out_scales)
{
    const float mx = __uint_as_float(g_max_bits);
    const float scale = mx * (1.0f / 127.0f);
    g_inv_scale = 127.0f / mx;
    out_scales[0] = scale;   // scale1
    out_scales[1] = scale;   // scale2
    g_max_bits = 0u;         // reset for next replay (runs after all pass1 atomics)
}

// ---------------------------------------------------------------------------
// Kernel 3: quantize, consuming x in REVERSE address order so the first waves
// read the most-recently-written (L2-resident) tail of x. Each block covers
// half a row (512 consecutive float4) -> inv_rms uniform per block.
//   q = clamp(rint(x * inv_rms[row] * gamma[col] * (127/max)), -128, 127)
// x reads: default policy (L2 hits on the resident tail; don't demote).
// y1/y2 stores: evict-first so they never displace x lines.
// ---------------------------------------------------------------------------
__global__ __launch_bounds__(256, 8)
void k_pass2(const float* __restrict__ xin,
             const float* __restrict__ gamma,
             float* __restrict__ y1,
             float* __restrict__ y2)
{
    const int t   = threadIdx.x;
    const int seg = (int)(gridDim.x - 1u - blockIdx.x);   // reversed mapping
    const size_t v0 = (size_t)seg * 512 + t;              // float4 index
    const size_t v1 = v0 + 256;
    const int row = (int)(v0 >> 10);                      // 1024 vec4 per row

    const float4* x4 = (const float4*)xin;
    const float4* g4 = (const float4*)gamma;

    float4 xa = x4[v0];
    float4 xb = x4[v1];
    float4 ga = g4[v0 & 1023];
    float4 gb = g4[v1 & 1023];

    const float s = g_inv_rms[row] * g_inv_scale;         // fold both scalars

    float4 qa, qb;
    qa.x = fminf(fmaxf(rintf(xa.x * ga.x * s), -128.0f), 127.0f);
    qa.y = fminf(fmaxf(rintf(xa.y * ga.y * s), -128.0f), 127.0f);
    qa.z = fminf(fmaxf(rintf(xa.z * ga.z * s), -128.0f), 127.0f);
    qa.w = fminf(fmaxf(rintf(xa.w * ga.w * s), -128.0f), 127.0f);
    qb.x = fminf(fmaxf(rintf(xb.x * gb.x * s), -128.0f), 127.0f);
    qb.y = fminf(fmaxf(rintf(xb.y * gb.y * s), -128.0f), 127.0f);
    qb.z = fminf(fmaxf(rintf(xb.z * gb.z * s), -128.0f), 127.0f);
    qb.w = fminf(fmaxf(rintf(xb.w * gb.w * s), -128.0f), 127.0f);

    __stcs((float4*)y1 + v0, qa);
    __stcs((float4*)y1 + v1, qb);
    __stcs((float4*)y2 + v0, qa);
    __stcs((float4*)y2 + v1, qb);
}

// ---------------------------------------------------------------------------
// Launch: out layout (float32): [y1 (64M)] [y2 (64M)] [x (64M)] [scale1] [scale2]
// ---------------------------------------------------------------------------
extern "C" void kernel_launch(void* const* d_in, const int* in_sizes, int n_in,
                              void* d_out, int out_size)
{
    const float* x1    = (const float*)d_in[0];
    const float* x2    = (const float*)d_in[1];
    const float* gamma = (const float*)d_in[2];
    // d_in[3], d_in[4] = smooth_scale1/2 — unused by the reference

    float* out    = (float*)d_out;
    float* y1     = out;
    float* y2     = out + N_ELEMS;
    float* out_x  = out + 2 * N_ELEMS;
    float* scales = out + 3 * N_ELEMS;

    k_pass1<<<N_ROWS, 512>>>(x1, x2, gamma, out_x);
    k_mid<<<1, 1>>>(scales);
    const int vec4   = (int)(N_ELEMS / 4);            // 16M float4
    const int blocks = vec4 / 512;                    // 32768
    k_pass2<<<blocks, 256>>>(out_x, gamma, y1, y2);
}

// round 6
// speedup vs baseline: 1.0384x; 1.0110x over previous
#include <cuda_runtime.h>
#include <stdint.h>

// Problem shape (fixed by the dataset): B=4, S=4096, H=4096
#define H_DIM   4096
#define N_ROWS  16384                       // B*S
#define N_ELEMS (N_ROWS * (size_t)H_DIM)    // 64M
#define EPS_F   1e-6f

// Rows >= this threshold get evict-normal x stores (retained L2 tail ~128MB,
// matching L2 capacity 126MB). Earlier rows cannot survive to pass2 anyway.
#define RETAIN_ROW 8192

// Scratch (no allocation allowed in kernel_launch)
__device__ float        g_inv_rms[N_ROWS];
__device__ unsigned int g_max_bits;         // zero-initialized at module load
__device__ float        g_inv_scale;

// ---------------------------------------------------------------------------
// Kernel 1: one CTA per row.
//   x = x1 + x2 -> out_x.  Store policy split by row:
//     row <  RETAIN_ROW : evict-first (cannot survive to pass2, don't pollute)
//     row >= RETAIN_ROW : evict-normal (tail retained in L2 for pass2)
//   inv_rms = rsqrt(mean(x^2) + eps) -> g_inv_rms[row]
//   block_max |x*gamma|*inv_rms -> atomicMax(g_max_bits)
// ---------------------------------------------------------------------------
__global__ __launch_bounds__(512, 2)
void k_pass1(const float* __restrict__ x1,
             const float* __restrict__ x2,
             const float* __restrict__ gamma,
             float* __restrict__ out_x)
{
    const int row = blockIdx.x;
    const int t   = threadIdx.x;           // 0..511
    const size_t base = (size_t)row * H_DIM;

    const float4* a4 = (const float4*)(x1 + base);
    const float4* b4 = (const float4*)(x2 + base);
    float4*       o4 = (float4*)(out_x + base);
    const float4* g4 = (const float4*)gamma;

    // two float4 chunks per thread: vec-index t and t+512 (row has 1024 vec4)
    float4 a0 = __ldcs(a4 + t);
    float4 a1 = __ldcs(a4 + t + 512);
    float4 b0 = __ldcs(b4 + t);
    float4 b1 = __ldcs(b4 + t + 512);

    float4 v0, v1;
    v0.x = a0.x + b0.x; v0.y = a0.y + b0.y; v0.z = a0.z + b0.z; v0.w = a0.w + b0.w;
    v1.x = a1.x + b1.x; v1.y = a1.y + b1.y; v1.z = a1.z + b1.z; v1.w = a1.w + b1.w;

    if (row >= RETAIN_ROW) {
        // evict-normal: retain this tail in L2 for pass2's reversed read
        o4[t]       = v0;
        o4[t + 512] = v1;
    } else {
        // evict-first: streamed out, don't occupy L2 ways
        __stcs(o4 + t,       v0);
        __stcs(o4 + t + 512, v1);
    }

    // sum of squares
    float ss = v0.x*v0.x + v0.y*v0.y + v0.z*v0.z + v0.w*v0.w
             + v1.x*v1.x + v1.y*v1.y + v1.z*v1.z + v1.w*v1.w;

    // block reduce sum (16 warps)
    __shared__ float s_red[16];
    __shared__ float s_inv;
    const int lane = t & 31;
    const int wid  = t >> 5;

    #pragma unroll
    for (int off = 16; off > 0; off >>= 1)
        ss += __shfl_xor_sync(0xffffffffu, ss, off);
    if (lane == 0) s_red[wid] = ss;
    __syncthreads();
    if (wid == 0) {
        float s = (lane < 16) ? s_red[lane] : 0.0f;
        #pragma unroll
        for (int off = 8; off > 0; off >>= 1)
            s += __shfl_xor_sync(0xffffffffu, s, off);
        if (lane == 0) {
            float inv = rsqrtf(s * (1.0f / H_DIM) + EPS_F);
            g_inv_rms[row] = inv;
            s_inv = inv;
        }
    }
    __syncthreads();
    const float inv = s_inv;

    // local max of |x * gamma|  (gamma: 16KB, L1/L2 resident -> default ld)
    float4 gm0 = g4[t];
    float4 gm1 = g4[t + 512];
    float m = fabsf(v0.x * gm0.x);
    m = fmaxf(m, fabsf(v0.y * gm0.y));
    m = fmaxf(m, fabsf(v0.z * gm0.z));
    m = fmaxf(m, fabsf(v0.w * gm0.w));
    m = fmaxf(m, fabsf(v1.x * gm1.x));
    m = fmaxf(m, fabsf(v1.y * gm1.y));
    m = fmaxf(m, fabsf(v1.z * gm1.z));
    m = fmaxf(m, fabsf(v1.w * gm1.w));

    // block reduce max (reuse shared after sync)
    #pragma unroll
    for (int off = 16; off > 0; off >>= 1)
        m = fmaxf(m, __shfl_xor_sync(0xffffffffu, m, off));
    __syncthreads();   // protect s_red reuse
    if (lane == 0) s_red[wid] = m;
    __syncthreads();
    if (wid == 0) {
        float mm = (lane < 16) ? s_red[lane] : 0.0f;
        #pragma unroll
        for (int off = 8; off > 0; off >>= 1)
            mm = fmaxf(mm, __shfl_xor_sync(0xffffffffu, mm, off));
        if (lane == 0) {
            // all candidates >= 0 so uint ordering == float ordering
            atomicMax(&g_max_bits, __float_as_uint(mm * inv));
        }
    }
}

// ---------------------------------------------------------------------------
// Kernel 2: scalar epilogue — write scale1/scale2, stash 127/max, reset
// accumulator for the next graph replay. Tiny; pollutes nothing.
// ---------------------------------------------------------------------------
__global__ void k_mid(float* __restrict__ out_scales)
{
    const float mx = __uint_as_float(g_max_bits);
    const float scale = mx * (1.0f / 127.0f);
    g_inv_scale = 127.0f / mx;
    out_scales[0] = scale;   // scale1
    out_scales[1] = scale;   // scale2
    g_max_bits = 0u;         // reset for next replay (runs after all pass1 atomics)
}

// ---------------------------------------------------------------------------
// Kernel 3: quantize, consuming x in REVERSE address order (hits the retained
// L2 tail first). x reads use last-use policy: each line is read exactly once,
// freeing it immediately gives later misses clean victims (no writeback stall
// — retained lines are dirty). y stores evict-first.
// ---------------------------------------------------------------------------
__global__ __launch_bounds__(256, 8)
void k_pass2(const float* __restrict__ xin,
             const float* __restrict__ gamma,
             float* __restrict__ y1,
             float* __restrict__ y2)
{
    const int t   = threadIdx.x;
    const int seg = (int)(gridDim.x - 1u - blockIdx.x);   // reversed mapping
    const size_t v0 = (size_t)seg * 512 + t;              // float4 index
    const size_t v1 = v0 + 256;
    const int row = (int)(v0 >> 10);                      // 1024 vec4 per row

    const float4* x4 = (const float4*)xin;
    const float4* g4 = (const float4*)gamma;

    float4 xa = __ldlu(x4 + v0);
    float4 xb = __ldlu(x4 + v1);
    float4 ga = g4[v0 & 1023];
    float4 gb = g4[v1 & 1023];

    const float s = g_inv_rms[row] * g_inv_scale;         // fold both scalars

    float4 qa, qb;
    qa.x = fminf(fmaxf(rintf(xa.x * ga.x * s), -128.0f), 127.0f);
    qa.y = fminf(fmaxf(rintf(xa.y * ga.y * s), -128.0f), 127.0f);
    qa.z = fminf(fmaxf(rintf(xa.z * ga.z * s), -128.0f), 127.0f);
    qa.w = fminf(fmaxf(rintf(xa.w * ga.w * s), -128.0f), 127.0f);
    qb.x = fminf(fmaxf(rintf(xb.x * gb.x * s), -128.0f), 127.0f);
    qb.y = fminf(fmaxf(rintf(xb.y * gb.y * s), -128.0f), 127.0f);
    qb.z = fminf(fmaxf(rintf(xb.z * gb.z * s), -128.0f), 127.0f);
    qb.w = fminf(fmaxf(rintf(xb.w * gb.w * s), -128.0f), 127.0f);

    __stcs((float4*)y1 + v0, qa);
    __stcs((float4*)y1 + v1, qb);
    __stcs((float4*)y2 + v0, qa);
    __stcs((float4*)y2 + v1, qb);
}

// ---------------------------------------------------------------------------
// Launch: out layout (float32): [y1 (64M)] [y2 (64M)] [x (64M)] [scale1] [scale2]
// ---------------------------------------------------------------------------
extern "C" void kernel_launch(void* const* d_in, const int* in_sizes, int n_in,
                              void* d_out, int out_size)
{
    const float* x1    = (const float*)d_in[0];
    const float* x2    = (const float*)d_in[1];
    const float* gamma = (const float*)d_in[2];
    // d_in[3], d_in[4] = smooth_scale1/2 — unused by the reference

    float* out    = (float*)d_out;
    float* y1     = out;
    float* y2     = out + N_ELEMS;
    float* out_x  = out + 2 * N_ELEMS;
    float* scales = out + 3 * N_ELEMS;

    k_pass1<<<N_ROWS, 512>>>(x1, x2, gamma, out_x);
    k_mid<<<1, 1>>>(scales);
    const int vec4   = (int)(N_ELEMS / 4);            // 16M float4
    const int blocks = vec4 / 512;                    // 32768
    k_pass2<<<blocks, 256>>>(out_x, gamma, y1, y2);
}